// round 2
// baseline (speedup 1.0000x reference)
#include <cuda_runtime.h>
#include <cstddef>

// Problem constants
#define Bg    16
#define Ntok  512
#define Din   256
#define Dout  256
#define Hh    8
#define HD    32
#define Eg    131072
#define MROWS (Bg * Ntok)          // 8192
#define SCALE 0.17677669529663687f // 1/sqrt(32)

// Scratch (device globals; no allocation allowed)
__device__ float    g_q[MROWS * Dout];
__device__ float    g_k[MROWS * Dout];
__device__ float    g_v[MROWS * Dout];
__device__ float    g_att[MROWS * Dout];
__device__ unsigned g_mask[Bg * Ntok * (Ntok / 32)];  // 131072 words

// ---------------------------------------------------------------------------
// Mask build: diag (self loops) + edge scatter
// ---------------------------------------------------------------------------
__global__ void mask_init_kernel(unsigned* __restrict__ mask) {
    int idx = blockIdx.x * 256 + threadIdx.x;       // < 131072
    int w = idx & 15;
    int r = (idx >> 4) & 511;
    mask[idx] = ((r >> 5) == w) ? (1u << (r & 31)) : 0u;
}

__global__ void mask_edges_kernel(const int* __restrict__ src,
                                  const int* __restrict__ dst,
                                  unsigned* __restrict__ mask) {
    int i = blockIdx.x * 256 + threadIdx.x;         // < E
    int s = src[i];
    int d = dst[i];
    int b = s >> 9;       // / 512
    int r = s & 511;
    int c = d & 511;
    atomicOr(&mask[((b << 9) + r) * 16 + (c >> 5)], 1u << (c & 31));
}

// ---------------------------------------------------------------------------
// GEMM: C[M,256] = A[M,256] @ W[256,256] + bias   (fp32, 128x128x16 tiles,
// 8x8 microtile per thread -> 4 FMA per smem float, FFMA-bound not LDS-bound)
// ---------------------------------------------------------------------------
#define BM 128
#define BN 128
#define BK 16

__device__ __forceinline__ void gemm_body(const float* __restrict__ A,
                                          const float* __restrict__ W,
                                          const float* __restrict__ bias,
                                          float* __restrict__ C) {
    __shared__ float As[BK][BM];   // transposed A tile
    __shared__ float Ws[BK][BN];

    int t   = threadIdx.x;            // 0..255
    int ty  = t >> 4;                 // 0..15
    int tx  = t & 15;                 // 0..15
    int row0 = blockIdx.x * BM;
    int col0 = blockIdx.y * BN;

    float acc[8][8];
#pragma unroll
    for (int i = 0; i < 8; i++)
#pragma unroll
        for (int j = 0; j < 8; j++) acc[i][j] = 0.f;

    for (int k0 = 0; k0 < 256; k0 += BK) {
        // Load A tile (128 rows x 16 cols) as float4, store transposed
#pragma unroll
        for (int i = 0; i < 2; i++) {
            int ff = t + i * 256;            // 0..511
            int r  = ff >> 2;                // 0..127
            int cg = (ff & 3) * 4;           // 0,4,8,12
            float4 va = *reinterpret_cast<const float4*>(
                A + (size_t)(row0 + r) * 256 + k0 + cg);
            As[cg + 0][r] = va.x;
            As[cg + 1][r] = va.y;
            As[cg + 2][r] = va.z;
            As[cg + 3][r] = va.w;
        }
        // Load W tile (16 rows x 128 cols)
#pragma unroll
        for (int i = 0; i < 2; i++) {
            int ff = t + i * 256;            // 0..511
            int r  = ff >> 5;                // 0..15
            int cg = (ff & 31) * 4;          // 0..124
            float4 vw = *reinterpret_cast<const float4*>(
                W + (size_t)(k0 + r) * 256 + col0 + cg);
            *reinterpret_cast<float4*>(&Ws[r][cg]) = vw;
        }
        __syncthreads();

#pragma unroll
        for (int kk = 0; kk < BK; kk++) {
            float a[8], b[8];
            *reinterpret_cast<float4*>(&a[0]) = *reinterpret_cast<float4*>(&As[kk][ty * 8]);
            *reinterpret_cast<float4*>(&a[4]) = *reinterpret_cast<float4*>(&As[kk][ty * 8 + 4]);
            *reinterpret_cast<float4*>(&b[0]) = *reinterpret_cast<float4*>(&Ws[kk][tx * 8]);
            *reinterpret_cast<float4*>(&b[4]) = *reinterpret_cast<float4*>(&Ws[kk][tx * 8 + 4]);
#pragma unroll
            for (int i = 0; i < 8; i++)
#pragma unroll
                for (int j = 0; j < 8; j++) acc[i][j] += a[i] * b[j];
        }
        __syncthreads();
    }

    // Epilogue: add bias, write fp32
#pragma unroll
    for (int i = 0; i < 8; i++) {
        int r = row0 + ty * 8 + i;
#pragma unroll
        for (int j = 0; j < 8; j += 4) {
            int c = col0 + tx * 8 + j;
            float4 o;
            o.x = acc[i][j + 0] + bias[c + 0];
            o.y = acc[i][j + 1] + bias[c + 1];
            o.z = acc[i][j + 2] + bias[c + 2];
            o.w = acc[i][j + 3] + bias[c + 3];
            *reinterpret_cast<float4*>(C + (size_t)r * 256 + c) = o;
        }
    }
}

// Fused Q/K/V projection: blockIdx.z selects which projection
__global__ __launch_bounds__(256) void gemm_qkv_kernel(
    const float* __restrict__ A,
    const float* W0, const float* b0, float* C0,
    const float* W1, const float* b1, float* C1,
    const float* W2, const float* b2, float* C2) {
    const float* W    = (blockIdx.z == 0) ? W0 : (blockIdx.z == 1) ? W1 : W2;
    const float* bias = (blockIdx.z == 0) ? b0 : (blockIdx.z == 1) ? b1 : b2;
    float*       C    = (blockIdx.z == 0) ? C0 : (blockIdx.z == 1) ? C1 : C2;
    gemm_body(A, W, bias, C);
}

__global__ __launch_bounds__(256) void gemm_bias_kernel(
    const float* __restrict__ A, const float* __restrict__ W,
    const float* __restrict__ bias, float* __restrict__ C) {
    gemm_body(A, W, bias, C);
}

// ---------------------------------------------------------------------------
// Sparse masked attention: one warp per (b, h, q); lane = head dim.
// Masked keys contribute exactly 0 (exp(-1e9 - m) == 0.0f in fp32), so
// iterating only set mask bits is numerically identical to the dense ref.
// ---------------------------------------------------------------------------
__global__ __launch_bounds__(256) void attn_kernel(
    const float* __restrict__ q, const float* __restrict__ k,
    const float* __restrict__ v, const unsigned* __restrict__ mask,
    float* __restrict__ att) {
    int gw   = blockIdx.x * 8 + (threadIdx.x >> 5);  // global warp id
    int lane = threadIdx.x & 31;
    int qi = gw & 511;
    int h  = (gw >> 9) & 7;
    int b  = gw >> 12;

    size_t qbase = ((size_t)(b * Ntok + qi)) * 256 + h * 32;
    float qv = q[qbase + lane];

    float m = -1e30f, l = 0.f, acc = 0.f;
    const unsigned* mrow = mask + ((b << 9) + qi) * 16;

#pragma unroll 1
    for (int w = 0; w < 16; w++) {
        unsigned bits = mrow[w];
        while (bits) {
            int bit = __ffs(bits) - 1;
            bits &= bits - 1;
            int j = (w << 5) + bit;
            size_t base = ((size_t)(b * Ntok + j)) * 256 + h * 32 + lane;
            float s = qv * k[base];
#pragma unroll
            for (int o = 16; o; o >>= 1) s += __shfl_xor_sync(0xffffffffu, s, o);
            s *= SCALE;
            float mn   = fmaxf(m, s);
            float corr = __expf(m - mn);
            float p    = __expf(s - mn);
            l   = l * corr + p;
            acc = acc * corr + p * v[base];
            m = mn;
        }
    }
    att[qbase + lane] = acc / l;
}

// ---------------------------------------------------------------------------
// Launch
// ---------------------------------------------------------------------------
extern "C" void kernel_launch(void* const* d_in, const int* in_sizes, int n_in,
                              void* d_out, int out_size) {
    const float* h   = (const float*)d_in[0];
    const int*   src = (const int*)d_in[1];
    const int*   dst = (const int*)d_in[2];
    const float* Wq  = (const float*)d_in[3];
    const float* bq  = (const float*)d_in[4];
    const float* Wk  = (const float*)d_in[5];
    const float* bk  = (const float*)d_in[6];
    const float* Wv  = (const float*)d_in[7];
    const float* bv  = (const float*)d_in[8];
    const float* Wo  = (const float*)d_in[9];
    const float* bo  = (const float*)d_in[10];
    float* out = (float*)d_out;

    float *pq, *pk, *pv, *patt;
    unsigned* pmask;
    cudaGetSymbolAddress((void**)&pq,    g_q);
    cudaGetSymbolAddress((void**)&pk,    g_k);
    cudaGetSymbolAddress((void**)&pv,    g_v);
    cudaGetSymbolAddress((void**)&patt,  g_att);
    cudaGetSymbolAddress((void**)&pmask, g_mask);

    // Mask build (independent of GEMMs; stream-ordered before attention)
    mask_init_kernel<<<Bg * Ntok * 16 / 256, 256>>>(pmask);
    mask_edges_kernel<<<Eg / 256, 256>>>(src, dst, pmask);

    // Q/K/V projections (fused grid over z)
    gemm_qkv_kernel<<<dim3(MROWS / BM, Dout / BN, 3), 256>>>(
        h, Wq, bq, pq, Wk, bk, pk, Wv, bv, pv);

    // Sparse masked attention
    attn_kernel<<<(Bg * Hh * Ntok) / 8, 256>>>(pq, pk, pv, pmask, patt);

    // Output projection straight into d_out
    gemm_bias_kernel<<<dim3(MROWS / BM, Dout / BN, 1), 256>>>(patt, Wo, bo, out);
}

// round 4
// speedup vs baseline: 1.3742x; 1.3742x over previous
#include <cuda_runtime.h>
#include <cstddef>

// Problem constants
#define Bg    16
#define Ntok  512
#define Din   256
#define Dout  256
#define Hh    8
#define HD    32
#define Eg    131072
#define MROWS (Bg * Ntok)          // 8192
#define SCALE 0.17677669529663687f // 1/sqrt(32)

// Scratch (device globals; no allocation allowed)
__device__ float    g_q[MROWS * Dout];
__device__ float    g_k[MROWS * Dout];
__device__ float    g_v[MROWS * Dout];
__device__ float    g_att[MROWS * Dout];
__device__ unsigned g_mask[Bg * Ntok * (Ntok / 32)];  // 131072 words

// ---------------------------------------------------------------------------
// Mask build: diag (self loops) + edge scatter
// ---------------------------------------------------------------------------
__global__ void mask_init_kernel(unsigned* __restrict__ mask) {
    int idx = blockIdx.x * 256 + threadIdx.x;       // < 131072
    int w = idx & 15;
    int r = (idx >> 4) & 511;
    mask[idx] = ((r >> 5) == w) ? (1u << (r & 31)) : 0u;
}

__global__ void mask_edges_kernel(const int* __restrict__ src,
                                  const int* __restrict__ dst,
                                  unsigned* __restrict__ mask) {
    int i = blockIdx.x * 256 + threadIdx.x;         // < E
    int s = src[i];
    int d = dst[i];
    int b = s >> 9;       // / 512
    int r = s & 511;
    int c = d & 511;
    atomicOr(&mask[((b << 9) + r) * 16 + (c >> 5)], 1u << (c & 31));
}

// ---------------------------------------------------------------------------
// GEMM: C[M,256] = A[M,256] @ W[256,256] + bias   (fp32, 128x128x16 tiles,
// 8x8 microtile per thread)
// ---------------------------------------------------------------------------
#define BM 128
#define BN 128
#define BK 16

__device__ __forceinline__ void gemm_body(const float* __restrict__ A,
                                          const float* __restrict__ W,
                                          const float* __restrict__ bias,
                                          float* __restrict__ C) {
    __shared__ float As[BK][BM];   // transposed A tile
    __shared__ float Ws[BK][BN];

    int t   = threadIdx.x;            // 0..255
    int ty  = t >> 4;                 // 0..15
    int tx  = t & 15;                 // 0..15
    int row0 = blockIdx.x * BM;
    int col0 = blockIdx.y * BN;

    float acc[8][8];
#pragma unroll
    for (int i = 0; i < 8; i++)
#pragma unroll
        for (int j = 0; j < 8; j++) acc[i][j] = 0.f;

    for (int k0 = 0; k0 < 256; k0 += BK) {
#pragma unroll
        for (int i = 0; i < 2; i++) {
            int ff = t + i * 256;            // 0..511
            int r  = ff >> 2;                // 0..127
            int cg = (ff & 3) * 4;           // 0,4,8,12
            float4 va = *reinterpret_cast<const float4*>(
                A + (size_t)(row0 + r) * 256 + k0 + cg);
            As[cg + 0][r] = va.x;
            As[cg + 1][r] = va.y;
            As[cg + 2][r] = va.z;
            As[cg + 3][r] = va.w;
        }
#pragma unroll
        for (int i = 0; i < 2; i++) {
            int ff = t + i * 256;            // 0..511
            int r  = ff >> 5;                // 0..15
            int cg = (ff & 31) * 4;          // 0..124
            float4 vw = *reinterpret_cast<const float4*>(
                W + (size_t)(k0 + r) * 256 + col0 + cg);
            *reinterpret_cast<float4*>(&Ws[r][cg]) = vw;
        }
        __syncthreads();

#pragma unroll
        for (int kk = 0; kk < BK; kk++) {
            float a[8], b[8];
            *reinterpret_cast<float4*>(&a[0]) = *reinterpret_cast<float4*>(&As[kk][ty * 8]);
            *reinterpret_cast<float4*>(&a[4]) = *reinterpret_cast<float4*>(&As[kk][ty * 8 + 4]);
            *reinterpret_cast<float4*>(&b[0]) = *reinterpret_cast<float4*>(&Ws[kk][tx * 8]);
            *reinterpret_cast<float4*>(&b[4]) = *reinterpret_cast<float4*>(&Ws[kk][tx * 8 + 4]);
#pragma unroll
            for (int i = 0; i < 8; i++)
#pragma unroll
                for (int j = 0; j < 8; j++) acc[i][j] += a[i] * b[j];
        }
        __syncthreads();
    }

#pragma unroll
    for (int i = 0; i < 8; i++) {
        int r = row0 + ty * 8 + i;
#pragma unroll
        for (int j = 0; j < 8; j += 4) {
            int c = col0 + tx * 8 + j;
            float4 o;
            o.x = acc[i][j + 0] + bias[c + 0];
            o.y = acc[i][j + 1] + bias[c + 1];
            o.z = acc[i][j + 2] + bias[c + 2];
            o.w = acc[i][j + 3] + bias[c + 3];
            *reinterpret_cast<float4*>(C + (size_t)r * 256 + c) = o;
        }
    }
}

__global__ __launch_bounds__(256) void gemm_qkv_kernel(
    const float* __restrict__ A,
    const float* W0, const float* b0, float* C0,
    const float* W1, const float* b1, float* C1,
    const float* W2, const float* b2, float* C2) {
    const float* W    = (blockIdx.z == 0) ? W0 : (blockIdx.z == 1) ? W1 : W2;
    const float* bias = (blockIdx.z == 0) ? b0 : (blockIdx.z == 1) ? b1 : b2;
    float*       C    = (blockIdx.z == 0) ? C0 : (blockIdx.z == 1) ? C1 : C2;
    gemm_body(A, W, bias, C);
}

__global__ __launch_bounds__(256) void gemm_bias_kernel(
    const float* __restrict__ A, const float* __restrict__ W,
    const float* __restrict__ bias, float* __restrict__ C) {
    gemm_body(A, W, bias, C);
}

// ---------------------------------------------------------------------------
// Sparse masked attention, all 8 heads per warp.
// Warp per (b,q). Lane = (head hg = lane>>2) x (sub = lane&3); each lane
// owns 8 consecutive dims of its head (2 x float4). Per edge the warp reads
// the k row and v row exactly once (coalesced 1KB each, fully used),
// computes 8 head dots with a 2-step 4-lane shuffle reduce, and updates 8
// online-softmax states in parallel. Masked keys contribute exactly 0
// (exp underflow), identical to the dense reference.
// ---------------------------------------------------------------------------
__global__ __launch_bounds__(256) void attn_kernel(
    const float* __restrict__ q, const float* __restrict__ k,
    const float* __restrict__ v, const unsigned* __restrict__ mask,
    float* __restrict__ att) {
    int gw   = blockIdx.x * 8 + (threadIdx.x >> 5);  // global (b,q) id, < 8192
    int lane = threadIdx.x & 31;
    int qi = gw & 511;
    int b  = gw >> 9;

    int off = lane * 8;                              // dim offset within 256
    size_t qrow = (size_t)gw * 256;
    float4 qa = *reinterpret_cast<const float4*>(q + qrow + off);
    float4 qb = *reinterpret_cast<const float4*>(q + qrow + off + 4);

    float m = -1e30f, l = 0.f;
    float acc[8];
#pragma unroll
    for (int d = 0; d < 8; d++) acc[d] = 0.f;

    const unsigned* mrow = mask + ((b << 9) + qi) * 16;
    size_t bbase = (size_t)(b << 9) * 256;

#pragma unroll 1
    for (int w = 0; w < 16; w++) {
        unsigned bits = mrow[w];
        while (bits) {
            int bit = __ffs(bits) - 1;
            bits &= bits - 1;
            int j = (w << 5) + bit;
            const float* krow = k + bbase + (size_t)j * 256 + off;
            const float* vrow = v + bbase + (size_t)j * 256 + off;
            float4 ka = *reinterpret_cast<const float4*>(krow);
            float4 kb = *reinterpret_cast<const float4*>(krow + 4);
            float4 va = *reinterpret_cast<const float4*>(vrow);
            float4 vb = *reinterpret_cast<const float4*>(vrow + 4);

            float s = qa.x * ka.x + qa.y * ka.y + qa.z * ka.z + qa.w * ka.w
                    + qb.x * kb.x + qb.y * kb.y + qb.z * kb.z + qb.w * kb.w;
            // reduce across the 4 lanes of this head group
            s += __shfl_xor_sync(0xffffffffu, s, 1);
            s += __shfl_xor_sync(0xffffffffu, s, 2);
            s *= SCALE;

            float mn   = fmaxf(m, s);
            float corr = __expf(m - mn);
            float p    = __expf(s - mn);
            l = l * corr + p;
            m = mn;
            acc[0] = acc[0] * corr + p * va.x;
            acc[1] = acc[1] * corr + p * va.y;
            acc[2] = acc[2] * corr + p * va.z;
            acc[3] = acc[3] * corr + p * va.w;
            acc[4] = acc[4] * corr + p * vb.x;
            acc[5] = acc[5] * corr + p * vb.y;
            acc[6] = acc[6] * corr + p * vb.z;
            acc[7] = acc[7] * corr + p * vb.w;
        }
    }

    float inv = 1.f / l;
    float4 oa, ob;
    oa.x = acc[0] * inv; oa.y = acc[1] * inv; oa.z = acc[2] * inv; oa.w = acc[3] * inv;
    ob.x = acc[4] * inv; ob.y = acc[5] * inv; ob.z = acc[6] * inv; ob.w = acc[7] * inv;
    *reinterpret_cast<float4*>(att + qrow + off)     = oa;
    *reinterpret_cast<float4*>(att + qrow + off + 4) = ob;
}

// ---------------------------------------------------------------------------
// Launch
// ---------------------------------------------------------------------------
extern "C" void kernel_launch(void* const* d_in, const int* in_sizes, int n_in,
                              void* d_out, int out_size) {
    const float* h   = (const float*)d_in[0];
    const int*   src = (const int*)d_in[1];
    const int*   dst = (const int*)d_in[2];
    const float* Wq  = (const float*)d_in[3];
    const float* bq  = (const float*)d_in[4];
    const float* Wk  = (const float*)d_in[5];
    const float* bk  = (const float*)d_in[6];
    const float* Wv  = (const float*)d_in[7];
    const float* bv  = (const float*)d_in[8];
    const float* Wo  = (const float*)d_in[9];
    const float* bo  = (const float*)d_in[10];
    float* out = (float*)d_out;

    float *pq, *pk, *pv, *patt;
    unsigned* pmask;
    cudaGetSymbolAddress((void**)&pq,    g_q);
    cudaGetSymbolAddress((void**)&pk,    g_k);
    cudaGetSymbolAddress((void**)&pv,    g_v);
    cudaGetSymbolAddress((void**)&patt,  g_att);
    cudaGetSymbolAddress((void**)&pmask, g_mask);

    // Mask build (independent of GEMMs; stream-ordered before attention)
    mask_init_kernel<<<Bg * Ntok * 16 / 256, 256>>>(pmask);
    mask_edges_kernel<<<Eg / 256, 256>>>(src, dst, pmask);

    // Q/K/V projections (fused grid over z)
    gemm_qkv_kernel<<<dim3(MROWS / BM, Dout / BN, 3), 256>>>(
        h, Wq, bq, pq, Wk, bk, pk, Wv, bv, pv);

    // Sparse masked attention (warp per (b,q), all heads)
    attn_kernel<<<MROWS / 8, 256>>>(pq, pk, pv, pmask, patt);

    // Output projection straight into d_out
    gemm_bias_kernel<<<dim3(MROWS / BM, Dout / BN, 1), 256>>>(patt, Wo, bo, out);
}

// round 6
// speedup vs baseline: 2.2941x; 1.6695x over previous
#include <cuda_runtime.h>
#include <cuda_bf16.h>
#include <cstdint>
#include <cstddef>

// Problem constants
#define Bg    16
#define Ntok  512
#define Din   256
#define Dout  256
#define Hh    8
#define HD    32
#define Eg    131072
#define MROWS (Bg * Ntok)          // 8192
#define SCALE 0.17677669529663687f // 1/sqrt(32)

// Scratch (device globals; no allocation allowed)
__device__ float    g_q[MROWS * Dout];
__device__ float    g_k[MROWS * Dout];
__device__ float    g_v[MROWS * Dout];
__device__ float    g_att[MROWS * Dout];
__device__ unsigned g_mask[Bg * Ntok * (Ntok / 32)];  // 131072 words
// Transposed + hi/lo-split weights: [4 weights][N=256 rows][K=256 cols] K-major
__device__ __align__(16) __nv_bfloat16 g_wt_hi[4 * 256 * 256];
__device__ __align__(16) __nv_bfloat16 g_wt_lo[4 * 256 * 256];

// ---------------------------------------------------------------------------
// Warp-MMA helpers (portable sm_80+ path; tcgen05 unavailable: harness PTX
// target is compute_100 without the 'a' suffix)
// ---------------------------------------------------------------------------
__device__ __forceinline__ void ldsm_x4(uint32_t addr, uint32_t* r) {
    asm volatile("ldmatrix.sync.aligned.m8n8.x4.shared.b16 {%0,%1,%2,%3}, [%4];"
                 : "=r"(r[0]), "=r"(r[1]), "=r"(r[2]), "=r"(r[3]) : "r"(addr));
}
__device__ __forceinline__ void ldsm_x2(uint32_t addr, uint32_t* r) {
    asm volatile("ldmatrix.sync.aligned.m8n8.x2.shared.b16 {%0,%1}, [%2];"
                 : "=r"(r[0]), "=r"(r[1]) : "r"(addr));
}
__device__ __forceinline__ void mma_bf16(float* c, const uint32_t* a, const uint32_t* b) {
    asm volatile(
        "mma.sync.aligned.m16n8k16.row.col.f32.bf16.bf16.f32 "
        "{%0,%1,%2,%3}, {%4,%5,%6,%7}, {%8,%9}, {%0,%1,%2,%3};"
        : "+f"(c[0]), "+f"(c[1]), "+f"(c[2]), "+f"(c[3])
        : "r"(a[0]), "r"(a[1]), "r"(a[2]), "r"(a[3]), "r"(b[0]), "r"(b[1]));
}
__device__ __forceinline__ uint32_t pack_bf2(__nv_bfloat16 a, __nv_bfloat16 b) {
    __nv_bfloat162 t(a, b);
    return *reinterpret_cast<uint32_t*>(&t);
}

// ---------------------------------------------------------------------------
// Weight prep: W[K=256][N=256] fp32 -> Wt_hi/Wt_lo[N][K] bf16 (transpose+split)
// ---------------------------------------------------------------------------
__global__ void wsplit_kernel(const float* __restrict__ Wq, const float* __restrict__ Wk,
                              const float* __restrict__ Wv, const float* __restrict__ Wo,
                              __nv_bfloat16* __restrict__ wt_hi,
                              __nv_bfloat16* __restrict__ wt_lo) {
    const float* W = (blockIdx.z == 0) ? Wq : (blockIdx.z == 1) ? Wk
                   : (blockIdx.z == 2) ? Wv : Wo;
    __shared__ float tile[32][33];
    int tx = threadIdx.x, ty = threadIdx.y;
    int n0 = blockIdx.x * 32, k0 = blockIdx.y * 32;
#pragma unroll
    for (int j = 0; j < 4; j++)
        tile[ty + 8 * j][tx] = W[(k0 + ty + 8 * j) * 256 + n0 + tx];
    __syncthreads();
    size_t wbase = (size_t)blockIdx.z * 65536;
#pragma unroll
    for (int j = 0; j < 4; j++) {
        int n = n0 + ty + 8 * j;
        int k = k0 + tx;
        float x = tile[tx][ty + 8 * j];
        __nv_bfloat16 hi = __float2bfloat16(x);
        __nv_bfloat16 lo = __float2bfloat16(x - __bfloat162float(hi));
        wt_hi[wbase + (size_t)n * 256 + k] = hi;
        wt_lo[wbase + (size_t)n * 256 + k] = lo;
    }
}

// ---------------------------------------------------------------------------
// Mask build: diag (self loops) + edge scatter
// ---------------------------------------------------------------------------
__global__ void mask_init_kernel(unsigned* __restrict__ mask) {
    int idx = blockIdx.x * 256 + threadIdx.x;
    int w = idx & 15;
    int r = (idx >> 4) & 511;
    mask[idx] = ((r >> 5) == w) ? (1u << (r & 31)) : 0u;
}

__global__ void mask_edges_kernel(const int* __restrict__ src,
                                  const int* __restrict__ dst,
                                  unsigned* __restrict__ mask) {
    int i = blockIdx.x * 256 + threadIdx.x;
    int s = src[i];
    int d = dst[i];
    int b = s >> 9;
    int r = s & 511;
    int c = d & 511;
    atomicOr(&mask[((b << 9) + r) * 16 + (c >> 5)], 1u << (c & 31));
}

// ---------------------------------------------------------------------------
// bf16 hi/lo split GEMM: C[128,128] = A[128,256] @ Wt^T + bias per block.
// 3-term Markidis: Ah*Bh + Ah*Bl + Al*Bh (lo*lo dropped, ~1.5e-5 rel).
// 512 threads = 16 warps (4m x 4n), warp tile 32x32, m16n8k16 mma.sync.
// smem row stride 40 halfs (80B) -> ldmatrix phases cover all 32 banks.
// ---------------------------------------------------------------------------
#define KCH   32                // K-chunk
#define NCHNK 8                 // 256 / 32
#define ASTR  40                // smem row stride in halfs

struct Pf {
    float4 a[2];
    uint4  bh, bl;
};

__device__ __forceinline__ void pf_load(Pf& p, const float* __restrict__ A,
                                        const __nv_bfloat16* __restrict__ wth,
                                        const __nv_bfloat16* __restrict__ wtl,
                                        int row0, int col0, int ch, int tid) {
#pragma unroll
    for (int i = 0; i < 2; i++) {
        int idx = tid + i * 512;
        int r = idx >> 3, f4 = idx & 7;
        p.a[i] = *reinterpret_cast<const float4*>(
            A + (size_t)(row0 + r) * 256 + ch * KCH + f4 * 4);
    }
    int r = tid >> 2, q = tid & 3;
    p.bh = *reinterpret_cast<const uint4*>(wth + (size_t)(col0 + r) * 256 + ch * KCH + q * 8);
    p.bl = *reinterpret_cast<const uint4*>(wtl + (size_t)(col0 + r) * 256 + ch * KCH + q * 8);
}

__device__ __forceinline__ void pf_store(const Pf& p,
                                         __nv_bfloat16* Ash, __nv_bfloat16* Asl,
                                         __nv_bfloat16* Bsh, __nv_bfloat16* Bsl,
                                         int tid) {
#pragma unroll
    for (int i = 0; i < 2; i++) {
        int idx = tid + i * 512;
        int r = idx >> 3, f4 = idx & 7;
        float4 va = p.a[i];
        __nv_bfloat16 h0 = __float2bfloat16(va.x), h1 = __float2bfloat16(va.y);
        __nv_bfloat16 h2 = __float2bfloat16(va.z), h3 = __float2bfloat16(va.w);
        __nv_bfloat16 l0 = __float2bfloat16(va.x - __bfloat162float(h0));
        __nv_bfloat16 l1 = __float2bfloat16(va.y - __bfloat162float(h1));
        __nv_bfloat16 l2 = __float2bfloat16(va.z - __bfloat162float(h2));
        __nv_bfloat16 l3 = __float2bfloat16(va.w - __bfloat162float(h3));
        uint2 sh, sl;
        sh.x = pack_bf2(h0, h1); sh.y = pack_bf2(h2, h3);
        sl.x = pack_bf2(l0, l1); sl.y = pack_bf2(l2, l3);
        *reinterpret_cast<uint2*>(&Ash[r * ASTR + f4 * 4]) = sh;
        *reinterpret_cast<uint2*>(&Asl[r * ASTR + f4 * 4]) = sl;
    }
    int r = tid >> 2, q = tid & 3;
    *reinterpret_cast<uint4*>(&Bsh[r * ASTR + q * 8]) = p.bh;
    *reinterpret_cast<uint4*>(&Bsl[r * ASTR + q * 8]) = p.bl;
}

__device__ __forceinline__ void mma_gemm_body(
    const float* __restrict__ A,
    const __nv_bfloat16* __restrict__ wth,
    const __nv_bfloat16* __restrict__ wtl,
    const float* __restrict__ bias,
    float* __restrict__ C, int row0, int col0) {
    __shared__ __align__(16) __nv_bfloat16 Ash[128 * ASTR];
    __shared__ __align__(16) __nv_bfloat16 Asl[128 * ASTR];
    __shared__ __align__(16) __nv_bfloat16 Bsh[128 * ASTR];
    __shared__ __align__(16) __nv_bfloat16 Bsl[128 * ASTR];

    int tid  = threadIdx.x;           // 0..511
    int wid  = tid >> 5;
    int lane = tid & 31;
    int wrow = (wid >> 2) * 32;       // warp m base in tile
    int wn   = (wid & 3) * 32;        // warp n base in tile

    uint32_t ah_b = (uint32_t)__cvta_generic_to_shared(Ash);
    uint32_t al_b = (uint32_t)__cvta_generic_to_shared(Asl);
    uint32_t bh_b = (uint32_t)__cvta_generic_to_shared(Bsh);
    uint32_t bl_b = (uint32_t)__cvta_generic_to_shared(Bsl);

    // per-lane ldmatrix address components
    int arow = wrow + (lane & 15);
    int ac8  = ((lane >> 4) & 1) * 8;
    int brow = wn + (lane & 7);
    int bc8  = ((lane >> 3) & 1) * 8;

    float acc[2][4][4];
#pragma unroll
    for (int mt = 0; mt < 2; mt++)
#pragma unroll
        for (int nt = 0; nt < 4; nt++)
#pragma unroll
            for (int i = 0; i < 4; i++) acc[mt][nt][i] = 0.f;

    Pf pf;
    pf_load(pf, A, wth, wtl, row0, col0, 0, tid);
    pf_store(pf, Ash, Asl, Bsh, Bsl, tid);
    __syncthreads();

#pragma unroll 1
    for (int ch = 0; ch < NCHNK; ch++) {
        if (ch + 1 < NCHNK)
            pf_load(pf, A, wth, wtl, row0, col0, ch + 1, tid);

#pragma unroll
        for (int ks = 0; ks < 2; ks++) {
            uint32_t ah[2][4], al[2][4], bh[4][2], bl[4][2];
#pragma unroll
            for (int mt = 0; mt < 2; mt++) {
                uint32_t off = (uint32_t)(((arow + mt * 16) * ASTR + ks * 16 + ac8) * 2);
                ldsm_x4(ah_b + off, ah[mt]);
                ldsm_x4(al_b + off, al[mt]);
            }
#pragma unroll
            for (int nt = 0; nt < 4; nt++) {
                uint32_t off = (uint32_t)(((brow + nt * 8) * ASTR + ks * 16 + bc8) * 2);
                ldsm_x2(bh_b + off, bh[nt]);
                ldsm_x2(bl_b + off, bl[nt]);
            }
#pragma unroll
            for (int mt = 0; mt < 2; mt++)
#pragma unroll
                for (int nt = 0; nt < 4; nt++) {
                    mma_bf16(acc[mt][nt], ah[mt], bh[nt]);
                    mma_bf16(acc[mt][nt], ah[mt], bl[nt]);
                    mma_bf16(acc[mt][nt], al[mt], bh[nt]);
                }
        }
        __syncthreads();
        if (ch + 1 < NCHNK) {
            pf_store(pf, Ash, Asl, Bsh, Bsl, tid);
            __syncthreads();
        }
    }

    // Epilogue
#pragma unroll
    for (int mt = 0; mt < 2; mt++) {
#pragma unroll
        for (int nt = 0; nt < 4; nt++) {
            int r = row0 + wrow + mt * 16 + (lane >> 2);
            int c = col0 + wn + nt * 8 + (lane & 3) * 2;
            float b0 = bias[c], b1 = bias[c + 1];
            float2 o0 = make_float2(acc[mt][nt][0] + b0, acc[mt][nt][1] + b1);
            float2 o1 = make_float2(acc[mt][nt][2] + b0, acc[mt][nt][3] + b1);
            *reinterpret_cast<float2*>(C + (size_t)r * 256 + c)       = o0;
            *reinterpret_cast<float2*>(C + (size_t)(r + 8) * 256 + c) = o1;
        }
    }
}

// QKV: grid (64, 2, 3); O: grid (64, 2)
__global__ __launch_bounds__(512, 1) void mma_qkv_kernel(
    const float* __restrict__ A,
    const __nv_bfloat16* __restrict__ wt_hi, const __nv_bfloat16* __restrict__ wt_lo,
    const float* bq, const float* bk, const float* bv,
    float* q, float* k, float* v) {
    int wsel = blockIdx.z;
    const float* bias = (wsel == 0) ? bq : (wsel == 1) ? bk : bv;
    float* C = (wsel == 0) ? q : (wsel == 1) ? k : v;
    mma_gemm_body(A, wt_hi + (size_t)wsel * 65536, wt_lo + (size_t)wsel * 65536,
                  bias, C, blockIdx.x * 128, blockIdx.y * 128);
}

__global__ __launch_bounds__(512, 1) void mma_o_kernel(
    const float* __restrict__ A,
    const __nv_bfloat16* __restrict__ wt_hi, const __nv_bfloat16* __restrict__ wt_lo,
    const float* __restrict__ bias, float* __restrict__ C) {
    mma_gemm_body(A, wt_hi + (size_t)3 * 65536, wt_lo + (size_t)3 * 65536,
                  bias, C, blockIdx.x * 128, blockIdx.y * 128);
}

// ---------------------------------------------------------------------------
// Sparse masked attention, all 8 heads per warp (unchanged; 31.9us measured).
// ---------------------------------------------------------------------------
__global__ __launch_bounds__(256) void attn_kernel(
    const float* __restrict__ q, const float* __restrict__ k,
    const float* __restrict__ v, const unsigned* __restrict__ mask,
    float* __restrict__ att) {
    int gw   = blockIdx.x * 8 + (threadIdx.x >> 5);
    int lane = threadIdx.x & 31;
    int qi = gw & 511;
    int b  = gw >> 9;

    int off = lane * 8;
    size_t qrow = (size_t)gw * 256;
    float4 qa = *reinterpret_cast<const float4*>(q + qrow + off);
    float4 qb = *reinterpret_cast<const float4*>(q + qrow + off + 4);

    float m = -1e30f, l = 0.f;
    float acc[8];
#pragma unroll
    for (int d = 0; d < 8; d++) acc[d] = 0.f;

    const unsigned* mrow = mask + ((b << 9) + qi) * 16;
    size_t bbase = (size_t)(b << 9) * 256;

#pragma unroll 1
    for (int w = 0; w < 16; w++) {
        unsigned bits = mrow[w];
        while (bits) {
            int bit = __ffs(bits) - 1;
            bits &= bits - 1;
            int j = (w << 5) + bit;
            const float* krow = k + bbase + (size_t)j * 256 + off;
            const float* vrow = v + bbase + (size_t)j * 256 + off;
            float4 ka = *reinterpret_cast<const float4*>(krow);
            float4 kb = *reinterpret_cast<const float4*>(krow + 4);
            float4 va = *reinterpret_cast<const float4*>(vrow);
            float4 vb = *reinterpret_cast<const float4*>(vrow + 4);

            float s = qa.x * ka.x + qa.y * ka.y + qa.z * ka.z + qa.w * ka.w
                    + qb.x * kb.x + qb.y * kb.y + qb.z * kb.z + qb.w * kb.w;
            s += __shfl_xor_sync(0xffffffffu, s, 1);
            s += __shfl_xor_sync(0xffffffffu, s, 2);
            s *= SCALE;

            float mn   = fmaxf(m, s);
            float corr = __expf(m - mn);
            float p    = __expf(s - mn);
            l = l * corr + p;
            m = mn;
            acc[0] = acc[0] * corr + p * va.x;
            acc[1] = acc[1] * corr + p * va.y;
            acc[2] = acc[2] * corr + p * va.z;
            acc[3] = acc[3] * corr + p * va.w;
            acc[4] = acc[4] * corr + p * vb.x;
            acc[5] = acc[5] * corr + p * vb.y;
            acc[6] = acc[6] * corr + p * vb.z;
            acc[7] = acc[7] * corr + p * vb.w;
        }
    }

    float inv = 1.f / l;
    float4 oa, ob;
    oa.x = acc[0] * inv; oa.y = acc[1] * inv; oa.z = acc[2] * inv; oa.w = acc[3] * inv;
    ob.x = acc[4] * inv; ob.y = acc[5] * inv; ob.z = acc[6] * inv; ob.w = acc[7] * inv;
    *reinterpret_cast<float4*>(att + qrow + off)     = oa;
    *reinterpret_cast<float4*>(att + qrow + off + 4) = ob;
}

// ---------------------------------------------------------------------------
// Launch
// ---------------------------------------------------------------------------
extern "C" void kernel_launch(void* const* d_in, const int* in_sizes, int n_in,
                              void* d_out, int out_size) {
    const float* h   = (const float*)d_in[0];
    const int*   src = (const int*)d_in[1];
    const int*   dst = (const int*)d_in[2];
    const float* Wq  = (const float*)d_in[3];
    const float* bq  = (const float*)d_in[4];
    const float* Wk  = (const float*)d_in[5];
    const float* bk  = (const float*)d_in[6];
    const float* Wv  = (const float*)d_in[7];
    const float* bv  = (const float*)d_in[8];
    const float* Wo  = (const float*)d_in[9];
    const float* bo  = (const float*)d_in[10];
    float* out = (float*)d_out;

    float *pq, *pk, *pv, *patt;
    unsigned* pmask;
    __nv_bfloat16 *pwh, *pwl;
    cudaGetSymbolAddress((void**)&pq,    g_q);
    cudaGetSymbolAddress((void**)&pk,    g_k);
    cudaGetSymbolAddress((void**)&pv,    g_v);
    cudaGetSymbolAddress((void**)&patt,  g_att);
    cudaGetSymbolAddress((void**)&pmask, g_mask);
    cudaGetSymbolAddress((void**)&pwh,   g_wt_hi);
    cudaGetSymbolAddress((void**)&pwl,   g_wt_lo);

    // Weight transpose + hi/lo split; mask build (all independent)
    wsplit_kernel<<<dim3(8, 8, 4), dim3(32, 8)>>>(Wq, Wk, Wv, Wo, pwh, pwl);
    mask_init_kernel<<<Bg * Ntok * 16 / 256, 256>>>(pmask);
    mask_edges_kernel<<<Eg / 256, 256>>>(src, dst, pmask);

    // Q/K/V projections via mma.sync bf16 split
    mma_qkv_kernel<<<dim3(MROWS / 128, 2, 3), 512>>>(
        h, pwh, pwl, bq, bk, bv, pq, pk, pv);

    // Sparse masked attention
    attn_kernel<<<MROWS / 8, 256>>>(pq, pk, pv, pmask, patt);

    // Output projection straight into d_out
    mma_o_kernel<<<dim3(MROWS / 128, 2), 512>>>(patt, pwh, pwl, bo, out);
}